// round 15
// baseline (speedup 1.0000x reference)
#include <cuda_runtime.h>
#include <math.h>

#define NN 50000
#define EE 800000
#define HH 64
#define LL 2048
#define G4 256   // 4*HH

// ---------------- scratch (static device globals; no allocation) ----------------
__device__ __align__(16) float g_deg[NN];
__device__ __align__(16) float g_dinv[NN];
__device__ __align__(16) float g_xw[NN*HH];
__device__ __align__(16) float g_z[NN*HH];
__device__ __align__(16) float g_proj[LL*G4];
__device__ __align__(16) float g_hs0[LL*HH];
__device__ __align__(16) float g_finalh[HH];
__device__ __align__(16) float g_logits[NN];
__device__ unsigned char g_mask[NN];
__device__ unsigned int g_maxcell;
__device__ float g_sumcell;
__device__ unsigned long long g_packed;

// ---------------- helpers ----------------
__device__ __forceinline__ unsigned fkey(float f) {
    unsigned u = __float_as_uint(f);
    return (u & 0x80000000u) ? ~u : (u | 0x80000000u);
}
__device__ __forceinline__ float keyToFloat(unsigned k) {
    return (k & 0x80000000u) ? __uint_as_float(k ^ 0x80000000u)
                             : __uint_as_float(~k);
}

// packed f32x2 ops (sm_103a FFMA2 path — only reachable via PTX)
__device__ __forceinline__ void fma2(unsigned long long &d, unsigned long long a,
                                     unsigned long long b, unsigned long long c) {
    asm("fma.rn.f32x2 %0, %1, %2, %3;" : "=l"(d) : "l"(a), "l"(b), "l"(c));
}
__device__ __forceinline__ unsigned long long add2(unsigned long long a, unsigned long long b) {
    unsigned long long d;
    asm("add.rn.f32x2 %0, %1, %2;" : "=l"(d) : "l"(a), "l"(b));
    return d;
}

// JAX threefry2x32 with key(1) -> (k0=0, k1=1)
__device__ __forceinline__ void threefry01(unsigned &x0, unsigned &x1) {
    const unsigned ks0 = 0u, ks1 = 1u, ks2 = 0u ^ 1u ^ 0x1BD11BDAu;
    x0 += ks0; x1 += ks1;
#define TF_RND(r) { x0 += x1; x1 = (x1 << r) | (x1 >> (32 - r)); x1 ^= x0; }
    TF_RND(13) TF_RND(15) TF_RND(26) TF_RND(6)   x0 += ks1; x1 += ks2 + 1u;
    TF_RND(17) TF_RND(29) TF_RND(16) TF_RND(24)  x0 += ks2; x1 += ks0 + 2u;
    TF_RND(13) TF_RND(15) TF_RND(26) TF_RND(6)   x0 += ks0; x1 += ks1 + 3u;
    TF_RND(17) TF_RND(29) TF_RND(16) TF_RND(24)  x0 += ks1; x1 += ks2 + 4u;
    TF_RND(13) TF_RND(15) TF_RND(26) TF_RND(6)   x0 += ks2; x1 += ks0 + 5u;
#undef TF_RND
}
// JAX gumbel: -log(-log(uniform(tiny, 1)))
__device__ __forceinline__ float gumbelf(unsigned bits) {
    float u01 = __uint_as_float((bits >> 9) | 0x3F800000u) - 1.0f;
    const float tiny = 1.17549435e-38f;
    float u = fmaxf(tiny, u01 + tiny);
    return -logf(-logf(u));
}

// ---------------- kernels ----------------

__global__ void initKernel() {
    int i = blockIdx.x * blockDim.x + threadIdx.x;
    int stride = gridDim.x * blockDim.x;
    for (int j = i; j < NN; j += stride) { g_deg[j] = 1.0f; g_mask[j] = 0; }
    if (i == 0) { g_maxcell = 0u; g_sumcell = 0.0f; g_packed = 0ull; }
}

__global__ void degMaskKernel(const int* __restrict__ ei, const float* __restrict__ ew,
                              const int* __restrict__ visited) {
    int i = blockIdx.x * blockDim.x + threadIdx.x;
    if (i < EE) atomicAdd(&g_deg[ei[EE + i]], ew[i]);   // dst = row 1
    if (i < LL) g_mask[visited[i]] = 1;
}

__global__ void dinvKernel() {
    int i = blockIdx.x * blockDim.x + threadIdx.x;
    if (i < NN) g_dinv[i] = 1.0f / sqrtf(g_deg[i]);     // deg >= 1 (self loop)
}

// xw = x @ W1 AND z = dinv^2*xw + b1 in one pass (selfBias fused)
__global__ void xwKernel(const float* __restrict__ x, const float* __restrict__ W,
                         const float* __restrict__ b1) {
    __shared__ float Wsm[HH * HH];
    __shared__ float xs[4 * HH];
    int tid = threadIdx.x;
    for (int i = tid; i < HH * HH; i += 256) Wsm[i] = W[i];
    int o = tid & 63, nl = tid >> 6;
    float bo = b1[o];
    for (int n0 = blockIdx.x * 4; n0 < NN; n0 += gridDim.x * 4) {
        __syncthreads();
        int gi = n0 * HH + tid;
        xs[tid] = (gi < NN * HH) ? x[gi] : 0.0f;
        __syncthreads();
        int n = n0 + nl;
        if (n < NN) {
            float acc = 0.0f;
            #pragma unroll
            for (int k = 0; k < HH; k++) acc += xs[nl * HH + k] * Wsm[k * HH + o];
            g_xw[n * HH + o] = acc;
            float dv = g_dinv[n];
            g_z[n * HH + o] = dv * dv * acc + bo;
        }
    }
}

// scatter messages: z[dst] += dinv[src]*ew*dinv[dst] * xw[src]   (16 threads/edge, float4 atomics)
__global__ void edgeMsgKernel(const int* __restrict__ ei, const float* __restrict__ ew) {
    long long gid = (long long)blockIdx.x * blockDim.x + threadIdx.x;
    int e = (int)(gid >> 4);
    int lane = (int)(gid & 15);
    if (e >= EE) return;
    int s = ei[e];
    int d = ei[EE + e];
    float norm = g_dinv[s] * ew[e] * g_dinv[d];
    float4 v = *((const float4*)(g_xw + (long long)s * HH) + lane);
    float4 m = make_float4(norm * v.x, norm * v.y, norm * v.z, norm * v.w);
    atomicAdd((float4*)(g_z + (long long)d * HH) + lane, m);
}

// proj[t][r] = sum_k src[row(t)][k] * Wih[r][k] + bih[r] + bhh[r]
__global__ void projKernel(const float* __restrict__ src, const int* __restrict__ gatherIdx,
                           const float* __restrict__ Wih, const float* __restrict__ bih,
                           const float* __restrict__ bhh, float* __restrict__ proj) {
    __shared__ float Wt[32 * 257];     // transposed half-K tile, padded
    __shared__ float ssm[32 * HH];
    __shared__ float bsm[G4];
    int tid = threadIdx.x;
    int t0 = blockIdx.x * 32;
    for (int i = tid; i < 32 * HH; i += 256) {
        int tt = i >> 6, k = i & 63;
        int row = gatherIdx ? gatherIdx[t0 + tt] : (t0 + tt);
        ssm[i] = src[(long long)row * HH + k];
    }
    bsm[tid] = bih[tid] + bhh[tid];
    float acc[32];
    #pragma unroll
    for (int t = 0; t < 32; t++) acc[t] = 0.0f;
    int r = tid;
    for (int half = 0; half < 2; half++) {
        __syncthreads();
        for (int i = tid; i < G4 * 32; i += 256) {
            int rr = i >> 5, kk = i & 31;
            Wt[kk * 257 + rr] = Wih[rr * HH + half * 32 + kk];
        }
        __syncthreads();
        #pragma unroll
        for (int kk = 0; kk < 32; kk++) {
            float w = Wt[kk * 257 + r];
            int k = half * 32 + kk;
            #pragma unroll
            for (int t = 0; t < 32; t++) acc[t] += w * ssm[t * HH + k];
        }
    }
    #pragma unroll
    for (int t = 0; t < 32; t++) proj[(long long)(t0 + t) * G4 + r] = acc[t] + bsm[r];
}

// sequential LSTM recurrence; one block, 256 threads.
// Warp-local gate exchange: warp w owns units 8w..8w+7; lane = gate*8 + uu.
// Gates stored unit-major (gsm[unit*4+gate], conflict-free STS, float4 LDS).
// __syncwarp for gate exchange + ONE __syncthreads per step (h double-buffered).
// Activations: single libm tanhf per thread per step (branch-free sigmoid
// via select around the tanh identity); no divides, no MUFU asm.
__global__ void recKernel(const float* __restrict__ proj, float* __restrict__ hsout,
                          const float* __restrict__ Whh) {
    __shared__ __align__(16) float hbuf[2][HH];
    __shared__ __align__(16) float gsm[G4];   // [unit*4 + gate]
    int j = threadIdx.x;
    int w = j >> 5, lane = j & 31;
    int g = lane >> 3;            // 0:i 1:f 2:g 3:o
    int uu = lane & 7;            // unit within warp
    int u = w * 8 + uu;           // 0..63
    int row = g * HH + u;         // gate-major row in Whh / proj
    bool isG = (g == 2);

    // pack Whh row: wp[q] = (Whh[row][2q], Whh[row][2q+1])
    unsigned long long wp[32];
    const ulonglong2* wrow = (const ulonglong2*)(Whh + row * HH);
    #pragma unroll
    for (int q = 0; q < 16; q++) { ulonglong2 v = wrow[q]; wp[2*q] = v.x; wp[2*q+1] = v.y; }

    float c = 0.0f, hlast = 0.0f;
    if (j < HH) { hbuf[0][j] = 0.0f; hbuf[1][j] = 0.0f; }
    __syncthreads();

    float pnext = proj[row];
    for (int t = 0; t < LL; t++) {
        float p = pnext;
        if (t + 1 < LL) pnext = proj[(t + 1) * G4 + row];
        int cur = t & 1, nxt = cur ^ 1;

        unsigned long long acc[4];
        #pragma unroll
        for (int q = 0; q < 4; q++) acc[q] = 0ull;
        const ulonglong2* hp = (const ulonglong2*)hbuf[cur];
        #pragma unroll
        for (int q = 0; q < 16; q++) {
            ulonglong2 h2 = hp[q];
            fma2(acc[(2*q)   & 3], wp[2*q],     h2.x, acc[(2*q)   & 3]);
            fma2(acc[(2*q+1) & 3], wp[2*q + 1], h2.y, acc[(2*q+1) & 3]);
        }
        acc[0] = add2(acc[0], acc[2]);
        acc[1] = add2(acc[1], acc[3]);
        acc[0] = add2(acc[0], acc[1]);
        float lo, hi;
        asm("mov.b64 {%0,%1}, %2;" : "=f"(lo), "=f"(hi) : "l"(acc[0]));
        float a = p + lo + hi;

        // single tanhf, branch-free sigmoid via identity
        float arg = isG ? a : (0.5f * a);
        float tv = tanhf(arg);
        gsm[u * 4 + g] = isG ? tv : fmaf(0.5f, tv, 0.5f);
        __syncwarp();

        if (lane < 8) {   // one tail thread per unit, warp-local gates
            float4 gates = *(const float4*)(gsm + u * 4);  // (i,f,g,o)
            c = fmaf(gates.y, c, gates.x * gates.z);
            float h = gates.w * tanhf(c);
            hlast = h;
            hbuf[nxt][u] = h;
            if (hsout) hsout[t * HH + u] = h;
        }
        __syncthreads();
    }
    if (lane < 8) g_finalh[u] = hlast;
}

// logits = mask ? -inf : z @ finalh ; running max (warp per node)
__global__ void scoresKernel() {
    __shared__ float hsm[HH];
    int tid = threadIdx.x;
    if (tid < HH) hsm[tid] = g_finalh[tid];
    __syncthreads();
    int lane = tid & 31;
    int warp = (blockIdx.x * blockDim.x + tid) >> 5;
    int nwarps = (gridDim.x * blockDim.x) >> 5;
    float h0 = hsm[lane * 2], h1 = hsm[lane * 2 + 1];
    unsigned localmax = 0u;
    for (int n = warp; n < NN; n += nwarps) {
        float2 zv = ((const float2*)g_z)[(long long)n * 32 + lane];
        float s = zv.x * h0 + zv.y * h1;
        #pragma unroll
        for (int o = 16; o; o >>= 1) s += __shfl_xor_sync(0xffffffffu, s, o);
        if (lane == 0) {
            float lg = g_mask[n] ? -INFINITY : s;
            g_logits[n] = lg;
            unsigned k = fkey(lg);
            if (k > localmax) localmax = k;
        }
    }
    if (lane == 0) atomicMax(&g_maxcell, localmax);
}

__global__ void expSumKernel(float* __restrict__ out, int off) {
    float mx = keyToFloat(g_maxcell);
    int i = blockIdx.x * blockDim.x + threadIdx.x;
    int stride = gridDim.x * blockDim.x;
    float local = 0.0f;
    for (int n = i; n < NN; n += stride) {
        float e = expf(g_logits[n] - mx);     // -inf -> 0
        out[off + n] = e;
        local += e;
    }
    #pragma unroll
    for (int o = 16; o; o >>= 1) local += __shfl_xor_sync(0xffffffffu, local, o);
    if ((threadIdx.x & 31) == 0) atomicAdd(&g_sumcell, local);
}

// gumbel + argmax: JAX categorical(key(1)), partitionable threefry:
// per element i, counter = (0, i), bits = out0 ^ out1.
__global__ void gumbelKernel() {
    int i = blockIdx.x * blockDim.x + threadIdx.x;
    unsigned long long best = 0ull;
    if (i < NN) {
        unsigned x0 = 0u, x1 = (unsigned)i;
        threefry01(x0, x1);
        unsigned bits = x0 ^ x1;
        float v = g_logits[i] + gumbelf(bits);
        best = ((unsigned long long)fkey(v) << 32) | (0xFFFFFFFFu - (unsigned)i);
    }
    #pragma unroll
    for (int o = 16; o; o >>= 1) {
        unsigned long long v = __shfl_xor_sync(0xffffffffu, best, o);
        if (v > best) best = v;
    }
    if ((threadIdx.x & 31) == 0 && best) atomicMax(&g_packed, best);
}

__global__ void finalizeKernel(float* __restrict__ out, int off) {
    float inv = 1.0f / g_sumcell;
    int i = blockIdx.x * blockDim.x + threadIdx.x;
    int stride = gridDim.x * blockDim.x;
    for (int n = i; n < NN; n += stride) out[off + n] *= inv;
    if (i == 0 && off > 0) {
        unsigned idx = 0xFFFFFFFFu - (unsigned)(g_packed & 0xFFFFFFFFull);
        out[0] = (float)idx;
    }
}

__global__ void writeNextIntKernel(int* out) {
    unsigned idx = 0xFFFFFFFFu - (unsigned)(g_packed & 0xFFFFFFFFull);
    out[0] = (int)idx;
}

// ---------------- launch ----------------
extern "C" void kernel_launch(void* const* d_in, const int* in_sizes, int n_in,
                              void* d_out, int out_size) {
    const float* x       = (const float*)d_in[0];
    const int*   ei      = (const int*)  d_in[1];
    const float* ew      = (const float*)d_in[2];
    const int*   visited = (const int*)  d_in[3];
    const float* W1      = (const float*)d_in[4];
    const float* b1      = (const float*)d_in[5];
    const float* Wih0 = (const float*)d_in[6];
    const float* Whh0 = (const float*)d_in[7];
    const float* bih0 = (const float*)d_in[8];
    const float* bhh0 = (const float*)d_in[9];
    const float* Wih1 = (const float*)d_in[10];
    const float* Whh1 = (const float*)d_in[11];
    const float* bih1 = (const float*)d_in[12];
    const float* bhh1 = (const float*)d_in[13];

    float *z_p, *hs0_p, *proj_p;
    cudaGetSymbolAddress((void**)&z_p,   g_z);
    cudaGetSymbolAddress((void**)&hs0_p, g_hs0);
    cudaGetSymbolAddress((void**)&proj_p, g_proj);

    initKernel<<<256, 256>>>();
    degMaskKernel<<<(EE + 255) / 256, 256>>>(ei, ew, visited);
    dinvKernel<<<(NN + 255) / 256, 256>>>();
    xwKernel<<<1024, 256>>>(x, W1, b1);   // also writes z = dinv^2*xw + b1
    edgeMsgKernel<<<(int)(((long long)EE * 16 + 255) / 256), 256>>>(ei, ew);

    projKernel<<<LL / 32, 256>>>(z_p, visited, Wih0, bih0, bhh0, proj_p);
    recKernel<<<1, 256>>>(proj_p, hs0_p, Whh0);
    projKernel<<<LL / 32, 256>>>(hs0_p, nullptr, Wih1, bih1, bhh1, proj_p);
    recKernel<<<1, 256>>>(proj_p, nullptr, Whh1);

    scoresKernel<<<296, 256>>>();
    gumbelKernel<<<(NN + 255) / 256, 256>>>();

    if (out_size >= NN) {
        int off = out_size - NN;                 // expected 1: [next_node, probs...]
        expSumKernel<<<296, 256>>>((float*)d_out, off);
        finalizeKernel<<<296, 256>>>((float*)d_out, off);
    } else {
        writeNextIntKernel<<<1, 1>>>((int*)d_out);
    }
}

// round 16
// speedup vs baseline: 1.0437x; 1.0437x over previous
#include <cuda_runtime.h>
#include <math.h>

#define NN 50000
#define EE 800000
#define HH 64
#define LL 2048
#define G4 256   // 4*HH

// ---------------- scratch (static device globals; no allocation) ----------------
__device__ __align__(16) float g_deg[NN];
__device__ __align__(16) float g_dinv[NN];
__device__ __align__(16) float g_xw[NN*HH];
__device__ __align__(16) float g_z[NN*HH];
__device__ __align__(16) float g_proj[LL*G4];
__device__ __align__(16) float g_hs0[LL*HH];
__device__ __align__(16) float g_finalh[HH];
__device__ __align__(16) float g_logits[NN];
__device__ unsigned char g_mask[NN];
__device__ unsigned int g_maxcell;
__device__ float g_sumcell;
__device__ unsigned long long g_packed;

// ---------------- helpers ----------------
__device__ __forceinline__ unsigned fkey(float f) {
    unsigned u = __float_as_uint(f);
    return (u & 0x80000000u) ? ~u : (u | 0x80000000u);
}
__device__ __forceinline__ float keyToFloat(unsigned k) {
    return (k & 0x80000000u) ? __uint_as_float(k ^ 0x80000000u)
                             : __uint_as_float(~k);
}

// packed f32x2 ops (sm_103a FFMA2 path — only reachable via PTX)
__device__ __forceinline__ void fma2(unsigned long long &d, unsigned long long a,
                                     unsigned long long b, unsigned long long c) {
    asm("fma.rn.f32x2 %0, %1, %2, %3;" : "=l"(d) : "l"(a), "l"(b), "l"(c));
}
__device__ __forceinline__ unsigned long long add2(unsigned long long a, unsigned long long b) {
    unsigned long long d;
    asm("add.rn.f32x2 %0, %1, %2;" : "=l"(d) : "l"(a), "l"(b));
    return d;
}

// JAX threefry2x32 with key(1) -> (k0=0, k1=1)
__device__ __forceinline__ void threefry01(unsigned &x0, unsigned &x1) {
    const unsigned ks0 = 0u, ks1 = 1u, ks2 = 0u ^ 1u ^ 0x1BD11BDAu;
    x0 += ks0; x1 += ks1;
#define TF_RND(r) { x0 += x1; x1 = (x1 << r) | (x1 >> (32 - r)); x1 ^= x0; }
    TF_RND(13) TF_RND(15) TF_RND(26) TF_RND(6)   x0 += ks1; x1 += ks2 + 1u;
    TF_RND(17) TF_RND(29) TF_RND(16) TF_RND(24)  x0 += ks2; x1 += ks0 + 2u;
    TF_RND(13) TF_RND(15) TF_RND(26) TF_RND(6)   x0 += ks0; x1 += ks1 + 3u;
    TF_RND(17) TF_RND(29) TF_RND(16) TF_RND(24)  x0 += ks1; x1 += ks2 + 4u;
    TF_RND(13) TF_RND(15) TF_RND(26) TF_RND(6)   x0 += ks2; x1 += ks0 + 5u;
#undef TF_RND
}
// JAX gumbel: -log(-log(uniform(tiny, 1)))
__device__ __forceinline__ float gumbelf(unsigned bits) {
    float u01 = __uint_as_float((bits >> 9) | 0x3F800000u) - 1.0f;
    const float tiny = 1.17549435e-38f;
    float u = fmaxf(tiny, u01 + tiny);
    return -logf(-logf(u));
}

// ---------------- kernels ----------------

__global__ void initKernel() {
    int i = blockIdx.x * blockDim.x + threadIdx.x;
    int stride = gridDim.x * blockDim.x;
    for (int j = i; j < NN; j += stride) { g_deg[j] = 1.0f; g_mask[j] = 0; }
    if (i == 0) { g_maxcell = 0u; g_sumcell = 0.0f; g_packed = 0ull; }
}

__global__ void degMaskKernel(const int* __restrict__ ei, const float* __restrict__ ew,
                              const int* __restrict__ visited) {
    int i = blockIdx.x * blockDim.x + threadIdx.x;
    if (i < EE) atomicAdd(&g_deg[ei[EE + i]], ew[i]);   // dst = row 1
    if (i < LL) g_mask[visited[i]] = 1;
}

__global__ void dinvKernel() {
    int i = blockIdx.x * blockDim.x + threadIdx.x;
    if (i < NN) g_dinv[i] = 1.0f / sqrtf(g_deg[i]);     // deg >= 1 (self loop)
}

// xw = x @ W1 AND z = dinv^2*xw + b1 in one pass (selfBias fused)
__global__ void xwKernel(const float* __restrict__ x, const float* __restrict__ W,
                         const float* __restrict__ b1) {
    __shared__ float Wsm[HH * HH];
    __shared__ float xs[4 * HH];
    int tid = threadIdx.x;
    for (int i = tid; i < HH * HH; i += 256) Wsm[i] = W[i];
    int o = tid & 63, nl = tid >> 6;
    float bo = b1[o];
    for (int n0 = blockIdx.x * 4; n0 < NN; n0 += gridDim.x * 4) {
        __syncthreads();
        int gi = n0 * HH + tid;
        xs[tid] = (gi < NN * HH) ? x[gi] : 0.0f;
        __syncthreads();
        int n = n0 + nl;
        if (n < NN) {
            float acc = 0.0f;
            #pragma unroll
            for (int k = 0; k < HH; k++) acc += xs[nl * HH + k] * Wsm[k * HH + o];
            g_xw[n * HH + o] = acc;
            float dv = g_dinv[n];
            g_z[n * HH + o] = dv * dv * acc + bo;
        }
    }
}

// scatter messages: z[dst] += dinv[src]*ew*dinv[dst] * xw[src]   (16 threads/edge, float4 atomics)
__global__ void edgeMsgKernel(const int* __restrict__ ei, const float* __restrict__ ew) {
    long long gid = (long long)blockIdx.x * blockDim.x + threadIdx.x;
    int e = (int)(gid >> 4);
    int lane = (int)(gid & 15);
    if (e >= EE) return;
    int s = ei[e];
    int d = ei[EE + e];
    float norm = g_dinv[s] * ew[e] * g_dinv[d];
    float4 v = *((const float4*)(g_xw + (long long)s * HH) + lane);
    float4 m = make_float4(norm * v.x, norm * v.y, norm * v.z, norm * v.w);
    atomicAdd((float4*)(g_z + (long long)d * HH) + lane, m);
}

// proj[t][r] = sum_k src[row(t)][k] * Wih[r][k] + bih[r] + bhh[r]
__global__ void projKernel(const float* __restrict__ src, const int* __restrict__ gatherIdx,
                           const float* __restrict__ Wih, const float* __restrict__ bih,
                           const float* __restrict__ bhh, float* __restrict__ proj) {
    __shared__ float Wt[32 * 257];     // transposed half-K tile, padded
    __shared__ float ssm[32 * HH];
    __shared__ float bsm[G4];
    int tid = threadIdx.x;
    int t0 = blockIdx.x * 32;
    for (int i = tid; i < 32 * HH; i += 256) {
        int tt = i >> 6, k = i & 63;
        int row = gatherIdx ? gatherIdx[t0 + tt] : (t0 + tt);
        ssm[i] = src[(long long)row * HH + k];
    }
    bsm[tid] = bih[tid] + bhh[tid];
    float acc[32];
    #pragma unroll
    for (int t = 0; t < 32; t++) acc[t] = 0.0f;
    int r = tid;
    for (int half = 0; half < 2; half++) {
        __syncthreads();
        for (int i = tid; i < G4 * 32; i += 256) {
            int rr = i >> 5, kk = i & 31;
            Wt[kk * 257 + rr] = Wih[rr * HH + half * 32 + kk];
        }
        __syncthreads();
        #pragma unroll
        for (int kk = 0; kk < 32; kk++) {
            float w = Wt[kk * 257 + r];
            int k = half * 32 + kk;
            #pragma unroll
            for (int t = 0; t < 32; t++) acc[t] += w * ssm[t * HH + k];
        }
    }
    #pragma unroll
    for (int t = 0; t < 32; t++) proj[(long long)(t0 + t) * G4 + r] = acc[t] + bsm[r];
}

// sequential LSTM recurrence; one block, 256 threads, Whh row packed in registers,
// dot products via fma.rn.f32x2. Exactly ONE libm tanhf per thread per step,
// branch-free (sigmoid via select-in/select-out of the tanh identity).
// (Byte-exact R14 structure — measured optimum.)
__global__ void recKernel(const float* __restrict__ proj, float* __restrict__ hsout,
                          const float* __restrict__ Whh) {
    __shared__ __align__(16) float hsm[HH];
    __shared__ float gsm[G4];
    int j = threadIdx.x;
    bool isG = ((j >> 6) == 2);   // gate 2 = g (tanh); others sigmoid

    // pack Whh row j: wp[q] = (Whh[j][2q], Whh[j][2q+1])
    unsigned long long wp[32];
    const ulonglong2* wrow = (const ulonglong2*)(Whh + j * HH);
    #pragma unroll
    for (int q = 0; q < 16; q++) { ulonglong2 v = wrow[q]; wp[2*q] = v.x; wp[2*q+1] = v.y; }

    float c = 0.0f;
    if (j < HH) hsm[j] = 0.0f;
    __syncthreads();

    float pnext = proj[j];
    for (int t = 0; t < LL; t++) {
        float p = pnext;
        if (t + 1 < LL) pnext = proj[(t + 1) * G4 + j];

        unsigned long long acc[4];
        #pragma unroll
        for (int q = 0; q < 4; q++) acc[q] = 0ull;
        const ulonglong2* hp = (const ulonglong2*)hsm;
        #pragma unroll
        for (int q = 0; q < 16; q++) {
            ulonglong2 h2 = hp[q];
            fma2(acc[(2*q)   & 3], wp[2*q],     h2.x, acc[(2*q)   & 3]);
            fma2(acc[(2*q+1) & 3], wp[2*q + 1], h2.y, acc[(2*q+1) & 3]);
        }
        acc[0] = add2(acc[0], acc[2]);
        acc[1] = add2(acc[1], acc[3]);
        acc[0] = add2(acc[0], acc[1]);
        float lo, hi;
        asm("mov.b64 {%0,%1}, %2;" : "=f"(lo), "=f"(hi) : "l"(acc[0]));
        float a = p + lo + hi;

        // single tanhf, branch-free: tanh for gate g, 0.5*tanh(a/2)+0.5 otherwise
        float arg = isG ? a : (0.5f * a);
        float tv = tanhf(arg);
        gsm[j] = isG ? tv : fmaf(0.5f, tv, 0.5f);
        __syncthreads();

        if (j < HH) {
            float ig = gsm[j];
            float fg = gsm[HH + j];
            float gg = gsm[2 * HH + j];
            float og = gsm[3 * HH + j];
            c = fmaf(fg, c, ig * gg);
            float h = og * tanhf(c);
            hsm[j] = h;
            if (hsout) hsout[t * HH + j] = h;
        }
        __syncthreads();
    }
    if (j < HH) g_finalh[j] = hsm[j];
}

// logits = mask ? -inf : z @ finalh ; running max (warp per node)
__global__ void scoresKernel() {
    __shared__ float hsm[HH];
    int tid = threadIdx.x;
    if (tid < HH) hsm[tid] = g_finalh[tid];
    __syncthreads();
    int lane = tid & 31;
    int warp = (blockIdx.x * blockDim.x + tid) >> 5;
    int nwarps = (gridDim.x * blockDim.x) >> 5;
    float h0 = hsm[lane * 2], h1 = hsm[lane * 2 + 1];
    unsigned localmax = 0u;
    for (int n = warp; n < NN; n += nwarps) {
        float2 zv = ((const float2*)g_z)[(long long)n * 32 + lane];
        float s = zv.x * h0 + zv.y * h1;
        #pragma unroll
        for (int o = 16; o; o >>= 1) s += __shfl_xor_sync(0xffffffffu, s, o);
        if (lane == 0) {
            float lg = g_mask[n] ? -INFINITY : s;
            g_logits[n] = lg;
            unsigned k = fkey(lg);
            if (k > localmax) localmax = k;
        }
    }
    if (lane == 0) atomicMax(&g_maxcell, localmax);
}

// exp-normalize pass FUSED with gumbel argmax (both read logits once).
// gumbel: JAX categorical(key(1)), partitionable threefry: counter=(0,n),
// bits = out0 ^ out1.
__global__ void expSumGumbelKernel(float* __restrict__ out, int off) {
    float mx = keyToFloat(g_maxcell);
    int i = blockIdx.x * blockDim.x + threadIdx.x;
    int stride = gridDim.x * blockDim.x;
    float local = 0.0f;
    unsigned long long best = 0ull;
    for (int n = i; n < NN; n += stride) {
        float lg = g_logits[n];
        float e = expf(lg - mx);              // -inf -> 0
        out[off + n] = e;
        local += e;
        unsigned x0 = 0u, x1 = (unsigned)n;
        threefry01(x0, x1);
        float v = lg + gumbelf(x0 ^ x1);
        unsigned long long pk = ((unsigned long long)fkey(v) << 32) | (0xFFFFFFFFu - (unsigned)n);
        if (pk > best) best = pk;
    }
    #pragma unroll
    for (int o = 16; o; o >>= 1) {
        local += __shfl_xor_sync(0xffffffffu, local, o);
        unsigned long long v = __shfl_xor_sync(0xffffffffu, best, o);
        if (v > best) best = v;
    }
    if ((threadIdx.x & 31) == 0) {
        atomicAdd(&g_sumcell, local);
        if (best) atomicMax(&g_packed, best);
    }
}

// standalone gumbel (fallback path when out_size < NN)
__global__ void gumbelKernel() {
    int i = blockIdx.x * blockDim.x + threadIdx.x;
    unsigned long long best = 0ull;
    if (i < NN) {
        unsigned x0 = 0u, x1 = (unsigned)i;
        threefry01(x0, x1);
        unsigned bits = x0 ^ x1;
        float v = g_logits[i] + gumbelf(bits);
        best = ((unsigned long long)fkey(v) << 32) | (0xFFFFFFFFu - (unsigned)i);
    }
    #pragma unroll
    for (int o = 16; o; o >>= 1) {
        unsigned long long v = __shfl_xor_sync(0xffffffffu, best, o);
        if (v > best) best = v;
    }
    if ((threadIdx.x & 31) == 0 && best) atomicMax(&g_packed, best);
}

__global__ void finalizeKernel(float* __restrict__ out, int off) {
    float inv = 1.0f / g_sumcell;
    int i = blockIdx.x * blockDim.x + threadIdx.x;
    int stride = gridDim.x * blockDim.x;
    for (int n = i; n < NN; n += stride) out[off + n] *= inv;
    if (i == 0 && off > 0) {
        unsigned idx = 0xFFFFFFFFu - (unsigned)(g_packed & 0xFFFFFFFFull);
        out[0] = (float)idx;
    }
}

__global__ void writeNextIntKernel(int* out) {
    unsigned idx = 0xFFFFFFFFu - (unsigned)(g_packed & 0xFFFFFFFFull);
    out[0] = (int)idx;
}

// ---------------- launch ----------------
extern "C" void kernel_launch(void* const* d_in, const int* in_sizes, int n_in,
                              void* d_out, int out_size) {
    const float* x       = (const float*)d_in[0];
    const int*   ei      = (const int*)  d_in[1];
    const float* ew      = (const float*)d_in[2];
    const int*   visited = (const int*)  d_in[3];
    const float* W1      = (const float*)d_in[4];
    const float* b1      = (const float*)d_in[5];
    const float* Wih0 = (const float*)d_in[6];
    const float* Whh0 = (const float*)d_in[7];
    const float* bih0 = (const float*)d_in[8];
    const float* bhh0 = (const float*)d_in[9];
    const float* Wih1 = (const float*)d_in[10];
    const float* Whh1 = (const float*)d_in[11];
    const float* bih1 = (const float*)d_in[12];
    const float* bhh1 = (const float*)d_in[13];

    float *z_p, *hs0_p, *proj_p;
    cudaGetSymbolAddress((void**)&z_p,   g_z);
    cudaGetSymbolAddress((void**)&hs0_p, g_hs0);
    cudaGetSymbolAddress((void**)&proj_p, g_proj);

    initKernel<<<256, 256>>>();
    degMaskKernel<<<(EE + 255) / 256, 256>>>(ei, ew, visited);
    dinvKernel<<<(NN + 255) / 256, 256>>>();
    xwKernel<<<1024, 256>>>(x, W1, b1);   // also writes z = dinv^2*xw + b1
    edgeMsgKernel<<<(int)(((long long)EE * 16 + 255) / 256), 256>>>(ei, ew);

    projKernel<<<LL / 32, 256>>>(z_p, visited, Wih0, bih0, bhh0, proj_p);
    recKernel<<<1, 256>>>(proj_p, hs0_p, Whh0);
    projKernel<<<LL / 32, 256>>>(hs0_p, nullptr, Wih1, bih1, bhh1, proj_p);
    recKernel<<<1, 256>>>(proj_p, nullptr, Whh1);

    scoresKernel<<<296, 256>>>();

    if (out_size >= NN) {
        int off = out_size - NN;                 // expected 1: [next_node, probs...]
        expSumGumbelKernel<<<296, 256>>>((float*)d_out, off);
        finalizeKernel<<<296, 256>>>((float*)d_out, off);
    } else {
        gumbelKernel<<<(NN + 255) / 256, 256>>>();
        writeNextIntKernel<<<1, 1>>>((int*)d_out);
    }
}